// round 1
// baseline (speedup 1.0000x reference)
#include <cuda_runtime.h>
#include <math.h>

#define NG 8
#define LG 1024
#define NH 8
#define HD 16
#define DS 64
#define NB 64          // NG*NH batches
#define NE 131072      // total edges
#define NN_NODES 8192  // NG*LG

// ---------------- scratch (static device globals; no allocations) ----------------
__device__ float g_S [64ULL*1024*1024];   // scatter target A[b,h,sl,dl]; reused as ping buffer
__device__ float g_P0[64ULL*1024*1024];   // M / ping buffer
__device__ float g_O0[64ULL*1024*1024];   // out ping
__device__ float g_O1[64ULL*1024*1024];   // out pong
__device__ float g_G [8ULL*1024*1024];    // G[b,l,t]
__device__ float g_e0[NH*NN_NODES];
__device__ float g_e1[NH*NN_NODES];
__device__ float g_dummy[NH*NN_NODES];
__device__ float g_w[NH*NN_NODES];        // dt_self, layout [h][n]
__device__ float g_nrm[NB*LG];            // 1/(rowsum + dummy + TOL)

__device__ __forceinline__ float softplusf(float x) {
    return (x > 15.f) ? x : log1pf(expf(x));
}

// ---------------- 1) zero the scatter buffer ----------------
__global__ void k_zero(float* __restrict__ p, size_t n) {
    size_t i = ((size_t)blockIdx.x * blockDim.x + threadIdx.x) * 4;
    size_t stride = (size_t)gridDim.x * blockDim.x * 4;
    float4 z = make_float4(0.f, 0.f, 0.f, 0.f);
    for (; i < n; i += stride) *(float4*)(p + i) = z;
}

// ---------------- 2) per-node prep ----------------
__global__ void k_node(const float* __restrict__ dt, const float* __restrict__ dt_bias) {
    int i = blockIdx.x * blockDim.x + threadIdx.x;
    if (i >= NN_NODES * NH) return;
    int n = i >> 3, h = i & 7;
    float b = dt_bias[h];
    const float* row = dt + (size_t)n * (NH * 4) + h * 4;
    g_e0   [h * NN_NODES + n] = -softplusf(row[0] + b);
    g_e1   [h * NN_NODES + n] = -softplusf(row[1] + b);
    g_dummy[h * NN_NODES + n] = expf(-softplusf(row[2] + b));
    g_w    [h * NN_NODES + n] = row[3];          // raw dt_self (no transform)
}

// ---------------- 3) edge scatter ----------------
__global__ void k_scatter(const int* __restrict__ ei) {
    int idx = blockIdx.x * blockDim.x + threadIdx.x;
    if (idx >= NE * NH) return;
    int e = idx >> 3, h = idx & 7;
    int s = ei[e], d = ei[NE + e];
    int b = s >> 10, sl = s & 1023, dl = d & 1023;
    float v = expf(0.5f * (g_e0[h * NN_NODES + s] + g_e1[h * NN_NODES + d]));
    atomicAdd(&g_S[(((size_t)(b * NH + h)) * LG + sl) * LG + dl], v);
}

// ---------------- 4a) row sums -> reciprocal normalizer ----------------
__global__ void k_norm() {
    int r = blockIdx.x * 8 + (threadIdx.x >> 5);   // global row in [0, NB*LG)
    int lane = threadIdx.x & 31;
    const float* row = g_S + (size_t)r * LG;
    float s = 0.f;
    for (int j = lane; j < LG; j += 32) s += row[j];
    #pragma unroll
    for (int o = 16; o; o >>= 1) s += __shfl_xor_sync(0xFFFFFFFFu, s, o);
    if (lane == 0) {
        int bh = r >> 10, l = r & 1023;
        int b = bh >> 3, h = bh & 7;
        g_nrm[r] = 1.f / (s + g_dummy[h * NN_NODES + b * LG + l] + 0.1f);
    }
}

// ---------------- 4b) M = A_norm^T ; O = I + M ----------------
__global__ void k_transpose() {
    __shared__ float t[32][33];
    int bh = blockIdx.z;
    int i0 = blockIdx.x * 32, j0 = blockIdx.y * 32;
    size_t off = (size_t)bh * LG * LG;
    const float* S = g_S + off;
    float* M = g_P0 + off;
    float* O = g_O0 + off;
    int tx = threadIdx.x, ty = threadIdx.y;     // (32, 8)
    #pragma unroll
    for (int k = 0; k < 4; k++) {
        int j = j0 + ty + k * 8;
        t[ty + k * 8][tx] = S[(size_t)j * LG + i0 + tx];
    }
    __syncthreads();
    #pragma unroll
    for (int k = 0; k < 4; k++) {
        int i = i0 + ty + k * 8;
        int j = j0 + tx;
        float v = t[tx][ty + k * 8] * g_nrm[bh * LG + j];
        M[(size_t)i * LG + j] = v;
        O[(size_t)i * LG + j] = v + (i == j ? 1.f : 0.f);
    }
}

// ---------------- 5) batched 1024x1024x1024 SGEMM: C = A@B (+Cadd) ----------------
__global__ void __launch_bounds__(256) k_sgemm(const float* __restrict__ A,
                                               const float* __restrict__ B,
                                               float* __restrict__ C,
                                               const float* __restrict__ Cadd) {
    const int L = 1024;
    size_t off = (size_t)blockIdx.z * L * L;
    A += off; B += off; C += off;
    if (Cadd) Cadd += off;

    __shared__ float As[16][64];
    __shared__ float Bs[16][64];

    int tid = threadIdx.x;
    int tx = tid & 15, ty = tid >> 4;
    int row0 = blockIdx.y * 64, col0 = blockIdx.x * 64;

    int aRow = tid >> 2,  aC4 = (tid & 3) << 2;
    int bRow = tid >> 4,  bC4 = (tid & 15) << 2;

    float acc[4][4] = {};

    for (int kt = 0; kt < 64; kt++) {
        float4 av = *(const float4*)(A + (size_t)(row0 + aRow) * L + kt * 16 + aC4);
        As[aC4 + 0][aRow] = av.x;
        As[aC4 + 1][aRow] = av.y;
        As[aC4 + 2][aRow] = av.z;
        As[aC4 + 3][aRow] = av.w;
        *(float4*)&Bs[bRow][bC4] =
            *(const float4*)(B + (size_t)(kt * 16 + bRow) * L + col0 + bC4);
        __syncthreads();
        #pragma unroll
        for (int k = 0; k < 16; k++) {
            float4 a = *(const float4*)&As[k][ty * 4];
            float4 b = *(const float4*)&Bs[k][tx * 4];
            acc[0][0] += a.x * b.x; acc[0][1] += a.x * b.y; acc[0][2] += a.x * b.z; acc[0][3] += a.x * b.w;
            acc[1][0] += a.y * b.x; acc[1][1] += a.y * b.y; acc[1][2] += a.y * b.z; acc[1][3] += a.y * b.w;
            acc[2][0] += a.z * b.x; acc[2][1] += a.z * b.y; acc[2][2] += a.z * b.z; acc[2][3] += a.z * b.w;
            acc[3][0] += a.w * b.x; acc[3][1] += a.w * b.y; acc[3][2] += a.w * b.z; acc[3][3] += a.w * b.w;
        }
        __syncthreads();
    }

    #pragma unroll
    for (int i = 0; i < 4; i++) {
        int r = row0 + ty * 4 + i;
        float4 addv = Cadd ? *(const float4*)(Cadd + (size_t)r * L + col0 + tx * 4)
                           : make_float4(0.f, 0.f, 0.f, 0.f);
        float4 o;
        o.x = acc[i][0] + addv.x;
        o.y = acc[i][1] + addv.y;
        o.z = acc[i][2] + addv.z;
        o.w = acc[i][3] + addv.w;
        *(float4*)(C + (size_t)r * L + col0 + tx * 4) = o;
    }
}

// ---------------- 6) G[b,l,t] = sum_d C[b,l,d] * B[b,t,d] ----------------
__global__ void __launch_bounds__(256) k_gmat(const float* __restrict__ Cm,
                                              const float* __restrict__ Bm) {
    __shared__ float Cs[64][65];
    __shared__ float Bs2[64][65];
    int b = blockIdx.z;
    int t0 = blockIdx.x * 64, l0 = blockIdx.y * 64;
    int tid = threadIdx.x;
    #pragma unroll
    for (int q = 0; q < 4; q++) {
        int idx = tid + q * 256;
        int r = idx >> 4, c4 = (idx & 15) * 4;
        float4 v = *(const float4*)(Cm + ((size_t)(b * LG + l0 + r)) * DS + c4);
        Cs[r][c4] = v.x; Cs[r][c4 + 1] = v.y; Cs[r][c4 + 2] = v.z; Cs[r][c4 + 3] = v.w;
        float4 w = *(const float4*)(Bm + ((size_t)(b * LG + t0 + r)) * DS + c4);
        Bs2[r][c4] = w.x; Bs2[r][c4 + 1] = w.y; Bs2[r][c4 + 2] = w.z; Bs2[r][c4 + 3] = w.w;
    }
    __syncthreads();
    int tx = tid & 15, ty = tid >> 4;
    float acc[4][4] = {};
    for (int d = 0; d < 64; d++) {
        float c[4], bb[4];
        #pragma unroll
        for (int i = 0; i < 4; i++) c[i]  = Cs[ty * 4 + i][d];
        #pragma unroll
        for (int j = 0; j < 4; j++) bb[j] = Bs2[tx * 4 + j][d];
        #pragma unroll
        for (int i = 0; i < 4; i++)
            #pragma unroll
            for (int j = 0; j < 4; j++)
                acc[i][j] += c[i] * bb[j];
    }
    #pragma unroll
    for (int i = 0; i < 4; i++)
        #pragma unroll
        for (int j = 0; j < 4; j++)
            g_G[((size_t)b * LG + l0 + ty * 4 + i) * LG + t0 + tx * 4 + j] = acc[i][j];
}

// ---------------- 7) y = ((Lmat . G) * dt_self_t) @ x_head + x ----------------
__global__ void __launch_bounds__(256) k_final(const float* __restrict__ O,
                                               const float* __restrict__ x,
                                               const float* __restrict__ Dp,
                                               float* __restrict__ out) {
    int bh = blockIdx.z;
    int b = bh >> 3, h = bh & 7;
    int l0 = blockIdx.x * 64;
    const float* Ob = O   + (size_t)bh * LG * LG;
    const float* Gb = g_G + (size_t)b  * LG * LG;

    __shared__ float Os[64][65];
    __shared__ float Gs[64][65];
    __shared__ float xs[64][17];
    __shared__ float ws[64];

    int tid = threadIdx.x;
    int l = tid & 63;
    int d0 = (tid >> 6) * 4;
    float acc[4] = {0.f, 0.f, 0.f, 0.f};

    for (int t0 = 0; t0 < LG; t0 += 64) {
        #pragma unroll
        for (int q = 0; q < 4; q++) {
            int idx = tid + q * 256;
            int r = idx >> 4, c4 = (idx & 15) * 4;
            float4 v = *(const float4*)(Ob + (size_t)(l0 + r) * LG + t0 + c4);
            Os[r][c4] = v.x; Os[r][c4 + 1] = v.y; Os[r][c4 + 2] = v.z; Os[r][c4 + 3] = v.w;
            float4 g = *(const float4*)(Gb + (size_t)(l0 + r) * LG + t0 + c4);
            Gs[r][c4] = g.x; Gs[r][c4 + 1] = g.y; Gs[r][c4 + 2] = g.z; Gs[r][c4 + 3] = g.w;
        }
        {
            int t = tid >> 2, d4 = (tid & 3) * 4;
            float4 v = *(const float4*)(x + (size_t)(b * LG + t0 + t) * 128 + h * HD + d4);
            xs[t][d4] = v.x; xs[t][d4 + 1] = v.y; xs[t][d4 + 2] = v.z; xs[t][d4 + 3] = v.w;
        }
        if (tid < 64) ws[tid] = g_w[h * NN_NODES + b * LG + t0 + tid];
        __syncthreads();
        #pragma unroll 8
        for (int tt = 0; tt < 64; tt++) {
            float a = Os[l][tt] * Gs[l][tt] * ws[tt];
            #pragma unroll
            for (int j = 0; j < 4; j++) acc[j] += a * xs[tt][d0 + j];
        }
        __syncthreads();
    }

    float dh = Dp[h];
    int n = b * LG + l0 + l;
    #pragma unroll
    for (int j = 0; j < 4; j++) {
        float xv = x[(size_t)n * 128 + h * HD + d0 + j];
        out[(size_t)n * 128 + (d0 + j) * NH + h] = acc[j] + xv * dh;   // out[n, d*8+h]
    }
}

// ---------------- host launcher ----------------
extern "C" void kernel_launch(void* const* d_in, const int* in_sizes, int n_in,
                              void* d_out, int out_size) {
    const float* x   = (const float*)d_in[0];
    const float* Bm  = (const float*)d_in[1];
    const float* Cm  = (const float*)d_in[2];
    const float* dt  = (const float*)d_in[3];
    const float* dtb = (const float*)d_in[4];
    const float* Dp  = (const float*)d_in[5];
    const int*   ei  = (const int*)  d_in[6];
    float* out = (float*)d_out;

    float *S, *P0, *O0, *O1;
    cudaGetSymbolAddress((void**)&S,  g_S);
    cudaGetSymbolAddress((void**)&P0, g_P0);
    cudaGetSymbolAddress((void**)&O0, g_O0);
    cudaGetSymbolAddress((void**)&O1, g_O1);

    size_t NNf = 64ULL * 1024 * 1024;
    k_zero<<<2048, 256>>>(S, NNf);
    k_node<<<(NN_NODES * NH + 255) / 256, 256>>>(dt, dtb);
    k_scatter<<<(NE * NH) / 256, 256>>>(ei);
    k_norm<<<(NB * LG) / 8, 256>>>();
    k_transpose<<<dim3(32, 32, NB), dim3(32, 8)>>>();

    dim3 mg(16, 16, NB), mb(256);
    float* Lc = P0; float* Ln = S;     // "last" ping-pong (M lives in P0; S free after transpose)
    float* Oc = O0; float* On = O1;    // "out" ping-pong
    for (int it = 0; it < 5; it++) {
        k_sgemm<<<mg, mb>>>(Lc, Lc, Ln, nullptr);  // last = last @ last
        k_sgemm<<<mg, mb>>>(Oc, Ln, On, Oc);       // out  = out + out @ last
        float* t;
        t = Lc; Lc = Ln; Ln = t;
        t = Oc; Oc = On; On = t;
    }

    k_gmat<<<dim3(16, 16, NG), 256>>>(Cm, Bm);
    k_final<<<dim3(16, 1, NB), 256>>>(Oc, x, Dp, out);
}